// round 3
// baseline (speedup 1.0000x reference)
#include <cuda_runtime.h>

#define NB   32
#define NCH  16
#define NP   65536              // 256*256 pixels per batch
#define NPIX (NB * NP)

// ---------------- scratch (device globals; no allocation allowed) ----------
// per batch: [0:16] sum_class0_S, [16:32] sum_all_S, [32:48] sum_class0_T,
//            [48:64] sum_all_T, [64] count_class0
__device__ float g_sum[NB][65];
__device__ float g_mean[NB][2][2][16];   // [b][tensor][class][channel]
__device__ float g_rden[NB][2][2];       // 1 / max(||mean||, 1e-8)
__device__ float g_acc;

// ---------------------------------------------------------------------------
__global__ void k_zero() {
    int i = blockIdx.x * blockDim.x + threadIdx.x;
    if (i < NB * 65) ((float*)g_sum)[i] = 0.0f;
    if (i == 0) g_acc = 0.0f;
}

__device__ __forceinline__ float warp_sum(float v) {
#pragma unroll
    for (int off = 16; off; off >>= 1)
        v += __shfl_xor_sync(0xffffffffu, v, off);
    return v;
}

// ---------------- pass 1: class-conditional sums of normalized features ----
__device__ __forceinline__ void p1_accum(const float4* __restrict__ Xv, int p4,
                                         float m0x, float m0y, float m0z, float m0w,
                                         float* aA, float* a0) {
    float4 v[NCH];
#pragma unroll
    for (int c = 0; c < NCH; c++) v[c] = Xv[c * (NP / 4) + p4];
    float ssx = 0.f, ssy = 0.f, ssz = 0.f, ssw = 0.f;
#pragma unroll
    for (int c = 0; c < NCH; c++) {
        ssx = fmaf(v[c].x, v[c].x, ssx);
        ssy = fmaf(v[c].y, v[c].y, ssy);
        ssz = fmaf(v[c].z, v[c].z, ssz);
        ssw = fmaf(v[c].w, v[c].w, ssw);
    }
    // matches x / max(sqrt(ss), 1e-12) for all representable inputs
    float ix = rsqrtf(fmaxf(ssx, 1e-24f));
    float iy = rsqrtf(fmaxf(ssy, 1e-24f));
    float iz = rsqrtf(fmaxf(ssz, 1e-24f));
    float iw = rsqrtf(fmaxf(ssw, 1e-24f));
    float wx = m0x * ix, wy = m0y * iy, wz = m0z * iz, ww = m0w * iw;
#pragma unroll
    for (int c = 0; c < NCH; c++) {
        float a = aA[c];
        a = fmaf(v[c].x, ix, a); a = fmaf(v[c].y, iy, a);
        a = fmaf(v[c].z, iz, a); a = fmaf(v[c].w, iw, a);
        aA[c] = a;
        float z = a0[c];
        z = fmaf(v[c].x, wx, z); z = fmaf(v[c].y, wy, z);
        z = fmaf(v[c].z, wz, z); z = fmaf(v[c].w, ww, z);
        a0[c] = z;
    }
}

__global__ __launch_bounds__(128) void k_pass1(const float* __restrict__ S,
                                               const float* __restrict__ T,
                                               const int* __restrict__ tg) {
    int b = blockIdx.y;
    int tid = threadIdx.x;

    float a0S[NCH], aAS[NCH], a0T[NCH], aAT[NCH];
#pragma unroll
    for (int c = 0; c < NCH; c++) { a0S[c] = 0.f; aAS[c] = 0.f; a0T[c] = 0.f; aAT[c] = 0.f; }
    float cnt0 = 0.0f;

    const float4* Sv = (const float4*)(S + (size_t)b * NCH * NP);
    const float4* Tv = (const float4*)(T + (size_t)b * NCH * NP);
    const int4* tv = (const int4*)(tg + (size_t)b * NP);

#pragma unroll 1
    for (int it = 0; it < 4; it++) {
        int p4 = (it * 32 + blockIdx.x) * 128 + tid;   // float4 index in [0, NP/4)
        int4 t = tv[p4];
        float m0x = (t.x == 0) ? 1.f : 0.f;
        float m0y = (t.y == 0) ? 1.f : 0.f;
        float m0z = (t.z == 0) ? 1.f : 0.f;
        float m0w = (t.w == 0) ? 1.f : 0.f;
        cnt0 += (m0x + m0y) + (m0z + m0w);

        p1_accum(Sv, p4, m0x, m0y, m0z, m0w, aAS, a0S);
        p1_accum(Tv, p4, m0x, m0y, m0z, m0w, aAT, a0T);
    }

    float* gs = g_sum[b];
    bool lane0 = ((tid & 31) == 0);
#pragma unroll
    for (int c = 0; c < NCH; c++) {
        float v0 = warp_sum(a0S[c]);
        float v1 = warp_sum(aAS[c]);
        float v2 = warp_sum(a0T[c]);
        float v3 = warp_sum(aAT[c]);
        if (lane0) {
            atomicAdd(&gs[c],      v0);
            atomicAdd(&gs[16 + c], v1);
            atomicAdd(&gs[32 + c], v2);
            atomicAdd(&gs[48 + c], v3);
        }
    }
    float vc = warp_sum(cnt0);
    if (lane0) atomicAdd(&gs[64], vc);
}

// ---------------- means + reciprocal norms --------------------------------
__global__ void k_means() {
    int b = blockIdx.x;
    int tid = threadIdx.x;          // 0..31
    int t = tid >> 4;               // tensor: 0=S, 1=T
    int c = tid & 15;
    const float* gs = g_sum[b];
    float cnt0 = gs[64];
    float s0 = gs[t * 32 + c];
    float sA = gs[t * 32 + 16 + c];
    float m0 = s0 / (cnt0 + 1e-6f);
    float m1 = (sA - s0) / ((float)NP - cnt0 + 1e-6f);
    g_mean[b][t][0][c] = m0;
    g_mean[b][t][1][c] = m1;
    float n0 = m0 * m0, n1 = m1 * m1;
#pragma unroll
    for (int off = 8; off; off >>= 1) {
        n0 += __shfl_xor_sync(0xffffffffu, n0, off);
        n1 += __shfl_xor_sync(0xffffffffu, n1, off);
    }
    if (c == 0) {
        g_rden[b][t][0] = 1.0f / fmaxf(sqrtf(n0), 1e-8f);
        g_rden[b][t][1] = 1.0f / fmaxf(sqrtf(n1), 1e-8f);
    }
}

// ---------------- pass 2: per-pixel pcsim + MSE reduction ------------------
__device__ __forceinline__ float4 p2_pcsim(const float4* __restrict__ Xv, int p4,
                                           const float* __restrict__ sm0,
                                           const float* __restrict__ sm1,
                                           float rd0, float rd1,
                                           float sx, float sy, float sz, float sw) {
    float4 v[NCH];
#pragma unroll
    for (int c = 0; c < NCH; c++) v[c] = Xv[c * (NP / 4) + p4];
    float ssx = 0.f, ssy = 0.f, ssz = 0.f, ssw = 0.f;
#pragma unroll
    for (int c = 0; c < NCH; c++) {
        ssx = fmaf(v[c].x, v[c].x, ssx);
        ssy = fmaf(v[c].y, v[c].y, ssy);
        ssz = fmaf(v[c].z, v[c].z, ssz);
        ssw = fmaf(v[c].w, v[c].w, ssw);
    }
    float ix = rsqrtf(fmaxf(ssx, 1e-24f));
    float iy = rsqrtf(fmaxf(ssy, 1e-24f));
    float iz = rsqrtf(fmaxf(ssz, 1e-24f));
    float iw = rsqrtf(fmaxf(ssw, 1e-24f));

    float d0x = 0.f, d0y = 0.f, d0z = 0.f, d0w = 0.f;
    float d1x = 0.f, d1y = 0.f, d1z = 0.f, d1w = 0.f;
#pragma unroll
    for (int c = 0; c < NCH; c++) {
        float m0 = sm0[c], m1 = sm1[c];
        d0x = fmaf(v[c].x, m0, d0x); d0y = fmaf(v[c].y, m0, d0y);
        d0z = fmaf(v[c].z, m0, d0z); d0w = fmaf(v[c].w, m0, d0w);
        d1x = fmaf(v[c].x, m1, d1x); d1y = fmaf(v[c].y, m1, d1y);
        d1z = fmaf(v[c].z, m1, d1z); d1w = fmaf(v[c].w, m1, d1w);
    }
    float4 r;
    r.x = __expf(sx * (d0x * rd0 - d1x * rd1) * ix);
    r.y = __expf(sy * (d0y * rd0 - d1y * rd1) * iy);
    r.z = __expf(sz * (d0z * rd0 - d1z * rd1) * iz);
    r.w = __expf(sw * (d0w * rd0 - d1w * rd1) * iw);
    return r;
}

__global__ __launch_bounds__(128) void k_pass2(const float* __restrict__ S,
                                               const float* __restrict__ T,
                                               const int* __restrict__ tg) {
    __shared__ float sm[64];    // [tensor][class][channel]
    __shared__ float srd[4];    // [tensor][class]
    __shared__ float sred[4];
    int b = blockIdx.y;
    int tid = threadIdx.x;
    if (tid < 64)               sm[tid]       = ((const float*)g_mean)[b * 64 + tid];
    else if (tid < 68)          srd[tid - 64] = ((const float*)g_rden)[b * 4 + (tid - 64)];
    __syncthreads();

    const float4* Sv = (const float4*)(S + (size_t)b * NCH * NP);
    const float4* Tv = (const float4*)(T + (size_t)b * NCH * NP);
    const int4* tv = (const int4*)(tg + (size_t)b * NP);

    float local = 0.0f;
#pragma unroll 1
    for (int it = 0; it < 4; it++) {
        int p4 = (it * 32 + blockIdx.x) * 128 + tid;
        int4 t = tv[p4];
        // sign: +1 if class 0 (cos_own - cos_other = cos0 - cos1), else -1
        float sx = (t.x == 0) ? 1.f : -1.f;
        float sy = (t.y == 0) ? 1.f : -1.f;
        float sz = (t.z == 0) ? 1.f : -1.f;
        float sw = (t.w == 0) ? 1.f : -1.f;

        float4 pS = p2_pcsim(Sv, p4, &sm[0],  &sm[16], srd[0], srd[1], sx, sy, sz, sw);
        float4 pT = p2_pcsim(Tv, p4, &sm[32], &sm[48], srd[2], srd[3], sx, sy, sz, sw);

        float dx = pS.x - pT.x, dy = pS.y - pT.y;
        float dz = pS.z - pT.z, dw = pS.w - pT.w;
        local = fmaf(dx, dx, local);
        local = fmaf(dy, dy, local);
        local = fmaf(dz, dz, local);
        local = fmaf(dw, dw, local);
    }

    local = warp_sum(local);
    if ((tid & 31) == 0) sred[tid >> 5] = local;
    __syncthreads();
    if (tid == 0) {
        float v = (sred[0] + sred[1]) + (sred[2] + sred[3]);
        atomicAdd(&g_acc, v);
    }
}

// ---------------------------------------------------------------------------
__global__ void k_fin(float* __restrict__ out) {
    out[0] = g_acc * (1.0f / (float)NPIX);
}

extern "C" void kernel_launch(void* const* d_in, const int* in_sizes, int n_in,
                              void* d_out, int out_size) {
    const float* S = (const float*)d_in[0];
    const float* T = (const float*)d_in[1];
    const int* tg = (const int*)d_in[2];
    float* out = (float*)d_out;

    k_zero<<<9, 256>>>();
    dim3 grid(32, NB);
    k_pass1<<<grid, 128>>>(S, T, tg);
    k_means<<<NB, 32>>>();
    k_pass2<<<grid, 128>>>(S, T, tg);
    k_fin<<<1, 1>>>(out);
}